// round 2
// baseline (speedup 1.0000x reference)
#include <cuda_runtime.h>

// ---------------------------------------------------------------------------
// NeuralODE (Dopri5, piecewise-constant actions) — fp32 SIMT baseline.
// B=1024 rows, T=64 saves, 2 substeps/interval, 6 stages/substep.
// 128 CTAs x 256 threads, 8 batch rows per CTA, full time loop in-kernel.
// ---------------------------------------------------------------------------

#define B_    1024
#define T_    64
#define OB_   64
#define AC_   16
#define AUG_  32
#define H_    256
#define IN_   112   // OB + AC + AUG
#define OUT_  96    // OB + AUG
#define R_    8     // rows per CTA
#define NCTA  (B_ / R_)   // 128
#define NTHR  256

// Transposed weights (k-major -> coalesced across output columns)
__device__ float g_W0t[IN_ * H_];    // [k<112][j<256]
__device__ float g_W1t[H_ * H_];     // [k<256][j<256]
__device__ float g_W2t[H_ * H_];
__device__ float g_W3t[H_ * OUT_];   // [k<256][j<96]

// Dopri5 Butcher tableau (fp32, matching reference constant rounding)
__constant__ float cAT[6][5] = {
    {0.f, 0.f, 0.f, 0.f, 0.f},
    {1.0f / 5.0f, 0.f, 0.f, 0.f, 0.f},
    {3.0f / 40.0f, 9.0f / 40.0f, 0.f, 0.f, 0.f},
    {44.0f / 45.0f, -56.0f / 15.0f, 32.0f / 9.0f, 0.f, 0.f},
    {19372.0f / 6561.0f, -25360.0f / 2187.0f, 64448.0f / 6561.0f, -212.0f / 729.0f, 0.f},
    {9017.0f / 3168.0f, -355.0f / 33.0f, 46732.0f / 5247.0f, 49.0f / 176.0f, -5103.0f / 18656.0f}
};
__constant__ float cB[6] = {
    35.0f / 384.0f, 0.0f, 500.0f / 1113.0f, 125.0f / 192.0f,
    -2187.0f / 6784.0f, 11.0f / 84.0f
};

__global__ void transpose_k(const float* __restrict__ W0, const float* __restrict__ W1,
                            const float* __restrict__ W2, const float* __restrict__ W3) {
    int i = blockIdx.x * blockDim.x + threadIdx.x;   // 65536 threads
    if (i < H_ * IN_)  { int j = i / IN_, k = i % IN_;  g_W0t[k * H_ + j] = W0[i]; }
    if (i < H_ * H_)   { int j = i >> 8, k = i & 255;   g_W1t[k * H_ + j] = W1[i];
                                                        g_W2t[k * H_ + j] = W2[i]; }
    if (i < OUT_ * H_) { int j = i >> 8, k = i & 255;   g_W3t[k * OUT_ + j] = W3[i]; }
}

// Hidden layer, N=256 outputs. Thread -> 4 cols x 2 rows. Weight loads are
// LDG.128, coalesced (warp covers 128 contiguous floats per k).
__device__ __forceinline__ void layer256(const float* __restrict__ Wt,
                                         const float* xin, int xstride, int Kq,
                                         float4 bv, bool relu,
                                         float* xout, int tid) {
    int j0 = (tid & 63) * 4;
    int rg = tid >> 6;
    const float* x0p = xin + (rg * 2) * xstride;
    const float* x1p = xin + (rg * 2 + 1) * xstride;
    const float* wp  = Wt + j0;
    float a00 = 0.f, a01 = 0.f, a02 = 0.f, a03 = 0.f;
    float a10 = 0.f, a11 = 0.f, a12 = 0.f, a13 = 0.f;
#pragma unroll 2
    for (int kq = 0; kq < Kq; kq++) {
        float4 x0 = *(const float4*)(x0p + kq * 4);
        float4 x1 = *(const float4*)(x1p + kq * 4);
        float4 w;
        w = *(const float4*)(wp + (kq * 4 + 0) * H_);
        a00 += w.x * x0.x; a01 += w.y * x0.x; a02 += w.z * x0.x; a03 += w.w * x0.x;
        a10 += w.x * x1.x; a11 += w.y * x1.x; a12 += w.z * x1.x; a13 += w.w * x1.x;
        w = *(const float4*)(wp + (kq * 4 + 1) * H_);
        a00 += w.x * x0.y; a01 += w.y * x0.y; a02 += w.z * x0.y; a03 += w.w * x0.y;
        a10 += w.x * x1.y; a11 += w.y * x1.y; a12 += w.z * x1.y; a13 += w.w * x1.y;
        w = *(const float4*)(wp + (kq * 4 + 2) * H_);
        a00 += w.x * x0.z; a01 += w.y * x0.z; a02 += w.z * x0.z; a03 += w.w * x0.z;
        a10 += w.x * x1.z; a11 += w.y * x1.z; a12 += w.z * x1.z; a13 += w.w * x1.z;
        w = *(const float4*)(wp + (kq * 4 + 3) * H_);
        a00 += w.x * x0.w; a01 += w.y * x0.w; a02 += w.z * x0.w; a03 += w.w * x0.w;
        a10 += w.x * x1.w; a11 += w.y * x1.w; a12 += w.z * x1.w; a13 += w.w * x1.w;
    }
    a00 += bv.x; a01 += bv.y; a02 += bv.z; a03 += bv.w;
    a10 += bv.x; a11 += bv.y; a12 += bv.z; a13 += bv.w;
    if (relu) {
        a00 = fmaxf(a00, 0.f); a01 = fmaxf(a01, 0.f); a02 = fmaxf(a02, 0.f); a03 = fmaxf(a03, 0.f);
        a10 = fmaxf(a10, 0.f); a11 = fmaxf(a11, 0.f); a12 = fmaxf(a12, 0.f); a13 = fmaxf(a13, 0.f);
    }
    *(float4*)(xout + (rg * 2) * H_ + j0)     = make_float4(a00, a01, a02, a03);
    *(float4*)(xout + (rg * 2 + 1) * H_ + j0) = make_float4(a10, a11, a12, a13);
}

// Output layer, N=96. 192 active threads: 1 row x 4 cols each.
__device__ __forceinline__ void layer96(const float* __restrict__ Wt,
                                        const float* xin, float4 bv,
                                        float* xout, int tid) {
    if (tid >= 192) return;
    int r  = tid / 24;
    int j0 = (tid - r * 24) * 4;
    const float* xp = xin + r * H_;
    float a0 = 0.f, a1 = 0.f, a2 = 0.f, a3 = 0.f;
#pragma unroll 2
    for (int kq = 0; kq < H_ / 4; kq++) {
        float4 x = *(const float4*)(xp + kq * 4);
        float4 w;
        w = *(const float4*)(Wt + (kq * 4 + 0) * OUT_ + j0);
        a0 += w.x * x.x; a1 += w.y * x.x; a2 += w.z * x.x; a3 += w.w * x.x;
        w = *(const float4*)(Wt + (kq * 4 + 1) * OUT_ + j0);
        a0 += w.x * x.y; a1 += w.y * x.y; a2 += w.z * x.y; a3 += w.w * x.y;
        w = *(const float4*)(Wt + (kq * 4 + 2) * OUT_ + j0);
        a0 += w.x * x.z; a1 += w.y * x.z; a2 += w.z * x.z; a3 += w.w * x.z;
        w = *(const float4*)(Wt + (kq * 4 + 3) * OUT_ + j0);
        a0 += w.x * x.w; a1 += w.y * x.w; a2 += w.z * x.w; a3 += w.w * x.w;
    }
    *(float4*)(xout + r * OUT_ + j0) =
        make_float4(a0 + bv.x, a1 + bv.y, a2 + bv.z, a3 + bv.w);
}

__global__ void __launch_bounds__(NTHR, 1)
node_kernel(const float* __restrict__ ob, const float* __restrict__ acs,
            const float* __restrict__ times,
            const float* __restrict__ b0, const float* __restrict__ b1,
            const float* __restrict__ b2, const float* __restrict__ b3,
            float* __restrict__ out) {
    __shared__ __align__(16) float sy [R_ * OUT_];          // state y      (8x96)
    __shared__ __align__(16) float sks[6 * R_ * OUT_];      // k1..k6
    __shared__ __align__(16) float sxs[R_ * IN_];           // stage input  (8x112)
    __shared__ __align__(16) float shA[R_ * H_];            // activations ping
    __shared__ __align__(16) float shB[R_ * H_];            // activations pong
    __shared__ __align__(16) float sacs[12 * R_ * AC_];     // prefetched actions
    __shared__ float sh[R_];                                // per-row substep h
    __shared__ int   sidx[12 * R_];                         // per-(stage,row) action idx

    const int tid  = threadIdx.x;
    const int row0 = blockIdx.x * R_;

    // Preload per-thread bias vectors
    const int j0 = (tid & 63) * 4;
    const float4 bv0 = *(const float4*)(b0 + j0);
    const float4 bv1 = *(const float4*)(b1 + j0);
    const float4 bv2 = *(const float4*)(b2 + j0);
    float4 bv3 = make_float4(0.f, 0.f, 0.f, 0.f);
    if (tid < 192) {
        int r3 = tid / 24;
        bv3 = *(const float4*)(b3 + (tid - r3 * 24) * 4);
    }

    // y0 = [ob, zeros(AUG)]; emit save slot t=0
    for (int idx = tid; idx < R_ * OUT_; idx += NTHR) {
        int r = idx / OUT_, e = idx - r * OUT_;
        float v = (e < OB_) ? ob[(row0 + r) * OB_ + e] : 0.0f;
        sy[idx] = v;
        if (e < OB_) out[(size_t)(row0 + r) * T_ * OB_ + e] = v;
    }
    __syncthreads();

    for (int j = 0; j < T_ - 1; j++) {
        // --- interval prologue: per-row h + all 12 stage action indices ---
        if (tid < R_) {
            const int r = tid;
            const float* tsr = times + (size_t)(row0 + r) * T_;
            const float t0 = tsr[j], t1 = tsr[j + 1];
            const float h = (t1 - t0) / 2.0f;          // N_SUB = 2
            sh[r] = h;
            for (int sub = 0; sub < 2; sub++) {
                const float t = t0 + (float)sub * h;
                float st[6];
                st[0] = t;
                st[1] = t + h / 5.0f;
                st[2] = t + (3.0f * h) / 10.0f;
                st[3] = t + (4.0f * h) / 5.0f;
                st[4] = t + (8.0f * h) / 9.0f;
                st[5] = t + h;
                for (int s = 0; s < 6; s++) {
                    int cnt = 0;                       // searchsorted(side='right')
                    for (int i = 0; i < T_; i++) cnt += (tsr[i] <= st[s]) ? 1 : 0;
                    int ai = cnt - 1;
                    ai = max(0, min(ai, T_ - 1));
                    sidx[(sub * 6 + s) * R_ + r] = ai;
                }
            }
        }
        __syncthreads();
        // Prefetch all 12 action vectors for this interval
        for (int idx = tid; idx < 12 * R_ * AC_; idx += NTHR) {
            int s12 = idx / (R_ * AC_);
            int rem = idx - s12 * (R_ * AC_);
            int r = rem >> 4, c = rem & 15;
            sacs[idx] = acs[(size_t)(row0 + r) * T_ * AC_ +
                            (size_t)sidx[s12 * R_ + r] * AC_ + c];
        }
        __syncthreads();

        for (int sub = 0; sub < 2; sub++) {
            for (int s = 0; s < 6; s++) {
                // Stage input: y + h * sum_i A[s][i] * k_i   (+ action tail)
                for (int idx = tid; idx < R_ * OUT_; idx += NTHR) {
                    int r = idx / OUT_, e = idx - r * OUT_;
                    float x = sy[idx];
                    if (s > 0) {
                        float acc = 0.0f;
                        for (int i = 0; i < s; i++)
                            acc += cAT[s][i] * sks[(i * R_ + r) * OUT_ + e];
                        x += sh[r] * acc;
                    }
                    sxs[r * IN_ + e] = x;
                }
                if (tid < R_ * AC_) {
                    int r = tid >> 4;
                    sxs[r * IN_ + OUT_ + (tid & 15)] =
                        sacs[(sub * 6 + s) * R_ * AC_ + tid];
                }
                __syncthreads();

                layer256(g_W0t, sxs, IN_, IN_ / 4, bv0, true, shA, tid);
                __syncthreads();
                layer256(g_W1t, shA, H_, H_ / 4, bv1, true, shB, tid);
                __syncthreads();
                layer256(g_W2t, shB, H_, H_ / 4, bv2, true, shA, tid);
                __syncthreads();
                layer96(g_W3t, shA, bv3, sks + s * R_ * OUT_, tid);
                __syncthreads();
            }
            // y += h * sum_i b_i * k_i
            for (int idx = tid; idx < R_ * OUT_; idx += NTHR) {
                int r = idx / OUT_, e = idx - r * OUT_;
                float acc = 0.0f;
                for (int i = 0; i < 6; i++)
                    acc += cB[i] * sks[(i * R_ + r) * OUT_ + e];
                sy[idx] += sh[r] * acc;
            }
            __syncthreads();
        }
        // Save observable part at t_{j+1}
        for (int idx = tid; idx < R_ * OB_; idx += NTHR) {
            int r = idx >> 6, c = idx & 63;
            out[(size_t)(row0 + r) * T_ * OB_ + (size_t)(j + 1) * OB_ + c] =
                sy[r * OUT_ + c];
        }
        __syncthreads();
    }
}

extern "C" void kernel_launch(void* const* d_in, const int* in_sizes, int n_in,
                              void* d_out, int out_size) {
    const float* ob    = (const float*)d_in[0];
    const float* acs   = (const float*)d_in[1];
    const float* times = (const float*)d_in[2];
    const float* W0    = (const float*)d_in[3];
    const float* b0    = (const float*)d_in[4];
    const float* W1    = (const float*)d_in[5];
    const float* b1    = (const float*)d_in[6];
    const float* W2    = (const float*)d_in[7];
    const float* b2    = (const float*)d_in[8];
    const float* W3    = (const float*)d_in[9];
    const float* b3    = (const float*)d_in[10];
    float* out = (float*)d_out;

    transpose_k<<<256, 256>>>(W0, W1, W2, W3);
    node_kernel<<<NCTA, NTHR>>>(ob, acs, times, b0, b1, b2, b3, out);
}

// round 3
// speedup vs baseline: 1.2829x; 1.2829x over previous
#include <cuda_runtime.h>

// ---------------------------------------------------------------------------
// NeuralODE (Dopri5, piecewise-constant actions) — fp32 SIMT, round 2.
// 128 CTAs x 512 threads (16 warps), 8 batch rows per CTA.
// Hidden layers: thread = 1 col x 4 rows, weights [k][j] -> LDG.32 coalesced,
//   1 L1 wavefront per load, 2 row-groups (2x weight reuse in L1).
// Output layer padded N=128 so all 16 warps work (thread = 1 col x 2 rows).
// ---------------------------------------------------------------------------

#define B_    1024
#define T_    64
#define OB_   64
#define AC_   16
#define AUG_  32
#define H_    256
#define IN_   112   // OB + AC + AUG
#define OUT_  96    // OB + AUG
#define R_    8     // rows per CTA
#define NCTA  (B_ / R_)   // 128
#define NTHR  512

// Transposed weights, k-major
__device__ float g_W0t[IN_ * H_];     // [k<112][j<256]
__device__ float g_W1t[H_ * H_];      // [k<256][j<256]
__device__ float g_W2t[H_ * H_];
__device__ float g_W3t[H_ * 128];     // [k<256][j<128], cols 96..127 zero

__constant__ float cAT[6][5] = {
    {0.f, 0.f, 0.f, 0.f, 0.f},
    {1.0f / 5.0f, 0.f, 0.f, 0.f, 0.f},
    {3.0f / 40.0f, 9.0f / 40.0f, 0.f, 0.f, 0.f},
    {44.0f / 45.0f, -56.0f / 15.0f, 32.0f / 9.0f, 0.f, 0.f},
    {19372.0f / 6561.0f, -25360.0f / 2187.0f, 64448.0f / 6561.0f, -212.0f / 729.0f, 0.f},
    {9017.0f / 3168.0f, -355.0f / 33.0f, 46732.0f / 5247.0f, 49.0f / 176.0f, -5103.0f / 18656.0f}
};
__constant__ float cB[6] = {
    35.0f / 384.0f, 0.0f, 500.0f / 1113.0f, 125.0f / 192.0f,
    -2187.0f / 6784.0f, 11.0f / 84.0f
};

__global__ void transpose_k(const float* __restrict__ W0, const float* __restrict__ W1,
                            const float* __restrict__ W2, const float* __restrict__ W3) {
    int i = blockIdx.x * blockDim.x + threadIdx.x;   // 65536 threads
    if (i < H_ * IN_)  { int j = i / IN_, k = i % IN_;  g_W0t[k * H_ + j] = W0[i]; }
    if (i < H_ * H_)   { int j = i >> 8, k = i & 255;   g_W1t[k * H_ + j] = W1[i];
                                                        g_W2t[k * H_ + j] = W2[i]; }
    if (i < H_ * 128)  { int k = i >> 7, j = i & 127;
                         g_W3t[k * 128 + j] = (j < OUT_) ? W3[j * H_ + k] : 0.0f; }
}

// Hidden layer (N=256). Thread: 1 col x 4 rows. warp w: rowgroup = w&1,
// col = (w>>1)*32 + lane. Weight loads: LDG.32, warp-coalesced 128B per k.
__device__ __forceinline__ void layer_h(const float* __restrict__ Wt,
                                        const float* __restrict__ xin, int xs, int Kq,
                                        float bias, float* __restrict__ xout,
                                        int rg, int col) {
    const float* xp = xin + rg * 4 * xs;
    const float* wp = Wt + col;
    float a0 = 0.f, a1 = 0.f, a2 = 0.f, a3 = 0.f;
#pragma unroll 4
    for (int k4 = 0; k4 < Kq; ++k4) {
        const int k = k4 * 4;
        const float w0 = wp[(k + 0) * H_];
        const float w1 = wp[(k + 1) * H_];
        const float w2 = wp[(k + 2) * H_];
        const float w3 = wp[(k + 3) * H_];
        const float4 x0 = *(const float4*)(xp + 0 * xs + k);
        const float4 x1 = *(const float4*)(xp + 1 * xs + k);
        const float4 x2 = *(const float4*)(xp + 2 * xs + k);
        const float4 x3 = *(const float4*)(xp + 3 * xs + k);
        a0 += w0 * x0.x; a0 += w1 * x0.y; a0 += w2 * x0.z; a0 += w3 * x0.w;
        a1 += w0 * x1.x; a1 += w1 * x1.y; a1 += w2 * x1.z; a1 += w3 * x1.w;
        a2 += w0 * x2.x; a2 += w1 * x2.y; a2 += w2 * x2.z; a2 += w3 * x2.w;
        a3 += w0 * x3.x; a3 += w1 * x3.y; a3 += w2 * x3.z; a3 += w3 * x3.w;
    }
    xout[(rg * 4 + 0) * H_ + col] = fmaxf(a0 + bias, 0.f);
    xout[(rg * 4 + 1) * H_ + col] = fmaxf(a1 + bias, 0.f);
    xout[(rg * 4 + 2) * H_ + col] = fmaxf(a2 + bias, 0.f);
    xout[(rg * 4 + 3) * H_ + col] = fmaxf(a3 + bias, 0.f);
}

// Output layer (N padded to 128, K=256). Thread: 1 col x 2 rows.
// warp w: rowgroup = w&3, col = (w>>2)*32 + lane. Store only col<96.
__device__ __forceinline__ void layer_o(const float* __restrict__ Wt,
                                        const float* __restrict__ xin,
                                        float bias, float* __restrict__ ks,
                                        int rg, int col) {
    const float* xp = xin + rg * 2 * H_;
    const float* wp = Wt + col;
    float a0 = 0.f, a1 = 0.f;
#pragma unroll 4
    for (int k4 = 0; k4 < H_ / 4; ++k4) {
        const int k = k4 * 4;
        const float w0 = wp[(k + 0) * 128];
        const float w1 = wp[(k + 1) * 128];
        const float w2 = wp[(k + 2) * 128];
        const float w3 = wp[(k + 3) * 128];
        const float4 x0 = *(const float4*)(xp + k);
        const float4 x1 = *(const float4*)(xp + H_ + k);
        a0 += w0 * x0.x; a0 += w1 * x0.y; a0 += w2 * x0.z; a0 += w3 * x0.w;
        a1 += w0 * x1.x; a1 += w1 * x1.y; a1 += w2 * x1.z; a1 += w3 * x1.w;
    }
    if (col < OUT_) {
        ks[(rg * 2 + 0) * OUT_ + col] = a0 + bias;
        ks[(rg * 2 + 1) * OUT_ + col] = a1 + bias;
    }
}

__global__ void __launch_bounds__(NTHR, 1)
node_kernel(const float* __restrict__ ob, const float* __restrict__ acs,
            const float* __restrict__ times,
            const float* __restrict__ b0, const float* __restrict__ b1,
            const float* __restrict__ b2, const float* __restrict__ b3,
            float* __restrict__ out) {
    __shared__ __align__(16) float sy [R_ * OUT_];
    __shared__ __align__(16) float sks[6 * R_ * OUT_];
    __shared__ __align__(16) float sxs[R_ * IN_];
    __shared__ __align__(16) float shA[R_ * H_];
    __shared__ __align__(16) float shB[R_ * H_];
    __shared__ __align__(16) float sacs[12 * R_ * AC_];
    __shared__ float sh[R_];
    __shared__ int   sidx[12 * R_];

    const int tid  = threadIdx.x;
    const int w    = tid >> 5;
    const int lane = tid & 31;
    const int row0 = blockIdx.x * R_;

    // Hidden-layer mapping (same col for all 3 hidden layers)
    const int rgH  = w & 1;
    const int colH = (w >> 1) * 32 + lane;
    const float bh0 = b0[colH];
    const float bh1 = b1[colH];
    const float bh2 = b2[colH];
    // Output-layer mapping
    const int rgO  = w & 3;
    const int colO = (w >> 2) * 32 + lane;
    const float bo = (colO < OUT_) ? b3[colO] : 0.0f;

    // y0 = [ob, zeros(AUG)]; emit save slot t=0
    for (int idx = tid; idx < R_ * OUT_; idx += NTHR) {
        int r = idx / OUT_, e = idx - r * OUT_;
        float v = (e < OB_) ? ob[(row0 + r) * OB_ + e] : 0.0f;
        sy[idx] = v;
        if (e < OB_) out[(size_t)(row0 + r) * T_ * OB_ + e] = v;
    }
    __syncthreads();

    for (int j = 0; j < T_ - 1; j++) {
        // --- interval prologue: per-row h + all 12 stage action indices ---
        if (tid < R_) {
            const int r = tid;
            const float* tsr = times + (size_t)(row0 + r) * T_;
            const float t0 = tsr[j], t1 = tsr[j + 1];
            const float h = (t1 - t0) / 2.0f;          // N_SUB = 2
            sh[r] = h;
            for (int sub = 0; sub < 2; sub++) {
                const float t = t0 + (float)sub * h;
                float st[6];
                st[0] = t;
                st[1] = t + h / 5.0f;
                st[2] = t + (3.0f * h) / 10.0f;
                st[3] = t + (4.0f * h) / 5.0f;
                st[4] = t + (8.0f * h) / 9.0f;
                st[5] = t + h;
                for (int s = 0; s < 6; s++) {
                    int cnt = 0;                       // searchsorted(side='right')
                    for (int i = 0; i < T_; i++) cnt += (tsr[i] <= st[s]) ? 1 : 0;
                    int ai = cnt - 1;
                    ai = max(0, min(ai, T_ - 1));
                    sidx[(sub * 6 + s) * R_ + r] = ai;
                }
            }
        }
        __syncthreads();
        for (int idx = tid; idx < 12 * R_ * AC_; idx += NTHR) {
            int s12 = idx / (R_ * AC_);
            int rem = idx - s12 * (R_ * AC_);
            int r = rem >> 4, c = rem & 15;
            sacs[idx] = acs[(size_t)(row0 + r) * T_ * AC_ +
                            (size_t)sidx[s12 * R_ + r] * AC_ + c];
        }
        __syncthreads();

        for (int sub = 0; sub < 2; sub++) {
            for (int s = 0; s < 6; s++) {
                // Stage input: y + h * sum_i A[s][i] * k_i   (+ action tail)
                for (int idx = tid; idx < R_ * OUT_; idx += NTHR) {
                    int r = idx / OUT_, e = idx - r * OUT_;
                    float x = sy[idx];
                    if (s > 0) {
                        float acc = 0.0f;
                        for (int i = 0; i < s; i++)
                            acc += cAT[s][i] * sks[(i * R_ + r) * OUT_ + e];
                        x += sh[r] * acc;
                    }
                    sxs[r * IN_ + e] = x;
                }
                if (tid < R_ * AC_) {
                    int r = tid >> 4;
                    sxs[r * IN_ + OUT_ + (tid & 15)] =
                        sacs[(sub * 6 + s) * R_ * AC_ + tid];
                }
                __syncthreads();

                layer_h(g_W0t, sxs, IN_, IN_ / 4, bh0, shA, rgH, colH);
                __syncthreads();
                layer_h(g_W1t, shA, H_, H_ / 4, bh1, shB, rgH, colH);
                __syncthreads();
                layer_h(g_W2t, shB, H_, H_ / 4, bh2, shA, rgH, colH);
                __syncthreads();
                layer_o(g_W3t, shA, bo, sks + s * R_ * OUT_, rgO, colO);
                __syncthreads();
            }
            // y += h * sum_i b_i * k_i
            for (int idx = tid; idx < R_ * OUT_; idx += NTHR) {
                int r = idx / OUT_, e = idx - r * OUT_;
                float acc = 0.0f;
                for (int i = 0; i < 6; i++)
                    acc += cB[i] * sks[(i * R_ + r) * OUT_ + e];
                sy[idx] += sh[r] * acc;
            }
            __syncthreads();
        }
        // Save observable part at t_{j+1}
        for (int idx = tid; idx < R_ * OB_; idx += NTHR) {
            int r = idx >> 6, c = idx & 63;
            out[(size_t)(row0 + r) * T_ * OB_ + (size_t)(j + 1) * OB_ + c] =
                sy[r * OUT_ + c];
        }
        __syncthreads();
    }
}

extern "C" void kernel_launch(void* const* d_in, const int* in_sizes, int n_in,
                              void* d_out, int out_size) {
    const float* ob    = (const float*)d_in[0];
    const float* acs   = (const float*)d_in[1];
    const float* times = (const float*)d_in[2];
    const float* W0    = (const float*)d_in[3];
    const float* b0    = (const float*)d_in[4];
    const float* W1    = (const float*)d_in[5];
    const float* b1    = (const float*)d_in[6];
    const float* W2    = (const float*)d_in[7];
    const float* b2    = (const float*)d_in[8];
    const float* W3    = (const float*)d_in[9];
    const float* b3    = (const float*)d_in[10];
    float* out = (float*)d_out;

    transpose_k<<<256, 256>>>(W0, W1, W2, W3);
    node_kernel<<<NCTA, NTHR>>>(ob, acs, times, b0, b1, b2, b3, out);
}